// round 3
// baseline (speedup 1.0000x reference)
#include <cuda_runtime.h>
#include <cuda_bf16.h>
#include <cstdint>

#define F_DIM   512
#define F4      (F_DIM / 4)     // 128 float4 per row
#define NGROUPS 1024
#define NPB     64              // nodes per block
#define CHUNK   8               // nodes per fast-path chunk (MLP depth)
#define OUTK    7

// Tiny scratch (no allocations allowed)
__device__ float g_out[NGROUPS * OUTK];   // partial dot sums, 28 KB
__device__ float g_cnt[NGROUPS];
__device__ int   g_batch_is64;

// ---------------------------------------------------------------------------
// Kernel 1: zero tiny scratch + probe batch dtype (thread 0).
// batch is sorted 0..1023 so the last element is nonzero; viewed as 32-bit
// words: int64 storage -> odd word indices (high words) are 0.
// ---------------------------------------------------------------------------
__global__ void zero_probe_kernel(const int* __restrict__ bw, int N) {
    int i = blockIdx.x * blockDim.x + threadIdx.x;
    if (i < NGROUPS * OUTK) g_out[i] = 0.0f;
    if (i < NGROUPS)        g_cnt[i] = 0.0f;
    if (i == 0) {
        int z = (bw[N - 1] == 0) + (bw[N - 3] == 0) + (bw[N - 5] == 0);
        g_batch_is64 = (z == 3) ? 1 : 0;
    }
}

// ---------------------------------------------------------------------------
// Kernel 2: fused segment-sum + projection.
// Block = 128 threads owns NPB consecutive nodes; thread t owns columns
// [4t,4t+4). Running float4 accumulator per group run; at group boundaries
// (block-uniform) dot against smem W and atomicAdd 7 floats + count.
// ---------------------------------------------------------------------------
__global__ __launch_bounds__(128)
void fused_kernel(const float4* __restrict__ x4,
                  const int* __restrict__ bw,
                  const float4* __restrict__ W4g,
                  int N)
{
    __shared__ float4 sW[OUTK * F4];      // 14336 B
    __shared__ int    sgid[NPB];
    __shared__ float  sred[4][OUTK];

    const int t  = threadIdx.x;
    const int n0 = blockIdx.x * NPB;
    const int nCnt = min(NPB, N - n0);
    if (nCnt <= 0) return;

    // Load W into smem (once per block)
    #pragma unroll
    for (int i = 0; i < OUTK; i++)
        sW[i * F4 + t] = W4g[i * F4 + t];

    // Preload group ids for this node span
    const int is64 = g_batch_is64;
    for (int i = t; i < nCnt; i += 128) {
        int g = is64 ? bw[2 * (n0 + i)] : bw[n0 + i];
        sgid[i] = min(max(g, 0), NGROUPS - 1);
    }
    __syncthreads();

    float4 acc = make_float4(0.f, 0.f, 0.f, 0.f);
    int cur = sgid[0];
    int run = 0;

    const int warp = t >> 5, lane = t & 31;

    // --- flush lambda: block reduction of 7 dots + atomics ---
    auto flush = [&](int gid, int runlen) {
        float p[OUTK];
        #pragma unroll
        for (int k = 0; k < OUTK; k++) {
            float4 w = sW[k * F4 + t];
            p[k] = acc.x * w.x + acc.y * w.y + acc.z * w.z + acc.w * w.w;
        }
        #pragma unroll
        for (int off = 16; off > 0; off >>= 1) {
            #pragma unroll
            for (int k = 0; k < OUTK; k++)
                p[k] += __shfl_xor_sync(0xffffffff, p[k], off);
        }
        if (lane == 0) {
            #pragma unroll
            for (int k = 0; k < OUTK; k++) sred[warp][k] = p[k];
        }
        __syncthreads();
        if (t < OUTK)
            atomicAdd(&g_out[gid * OUTK + t],
                      sred[0][t] + sred[1][t] + sred[2][t] + sred[3][t]);
        if (t == OUTK)
            atomicAdd(&g_cnt[gid], (float)runlen);
        __syncthreads();
    };

    int i = 0;
    // Fast path: 8-node chunks entirely inside the current group (sorted ids
    // => first==last==cur implies all equal). Branch-free, 8 batched LDG.128.
    for (; i + CHUNK <= nCnt; i += CHUNK) {
        if (sgid[i] == cur && sgid[i + CHUNK - 1] == cur) {
            float4 v[CHUNK];
            #pragma unroll
            for (int j = 0; j < CHUNK; j++)
                v[j] = x4[(size_t)(n0 + i + j) * F4 + t];
            // pairwise tree sum to shorten the dependence chain
            #pragma unroll
            for (int j = 0; j < CHUNK; j += 2) {
                v[j].x += v[j+1].x; v[j].y += v[j+1].y;
                v[j].z += v[j+1].z; v[j].w += v[j+1].w;
            }
            v[0].x += v[2].x; v[0].y += v[2].y; v[0].z += v[2].z; v[0].w += v[2].w;
            v[4].x += v[6].x; v[4].y += v[6].y; v[4].z += v[6].z; v[4].w += v[6].w;
            acc.x += v[0].x + v[4].x;
            acc.y += v[0].y + v[4].y;
            acc.z += v[0].z + v[4].z;
            acc.w += v[0].w + v[4].w;
            run += CHUNK;
        } else {
            #pragma unroll
            for (int j = 0; j < CHUNK; j++) {
                int g = sgid[i + j];
                if (g != cur) {
                    flush(cur, run);
                    acc = make_float4(0.f, 0.f, 0.f, 0.f);
                    cur = g; run = 0;
                }
                float4 v = x4[(size_t)(n0 + i + j) * F4 + t];
                acc.x += v.x; acc.y += v.y; acc.z += v.z; acc.w += v.w;
                run++;
            }
        }
    }
    // tail
    for (; i < nCnt; i++) {
        int g = sgid[i];
        if (g != cur) {
            flush(cur, run);
            acc = make_float4(0.f, 0.f, 0.f, 0.f);
            cur = g; run = 0;
        }
        float4 v = x4[(size_t)(n0 + i) * F4 + t];
        acc.x += v.x; acc.y += v.y; acc.z += v.z; acc.w += v.w;
        run++;
    }
    flush(cur, run);
}

// ---------------------------------------------------------------------------
// Kernel 3: out[g][k] = g_out[g][k] / max(cnt[g],1) + b[k]
// grid = OUTK blocks x 1024 threads
// ---------------------------------------------------------------------------
__global__ void finalize_kernel(const float* __restrict__ b,
                                float* __restrict__ out)
{
    const int g = threadIdx.x;       // 0..1023
    const int k = blockIdx.x;        // 0..6
    float c = g_cnt[g];
    out[g * OUTK + k] = g_out[g * OUTK + k] / fmaxf(c, 1.0f) + b[k];
}

// ---------------------------------------------------------------------------
// Inputs (metadata order):
//   d_in[0] = x          float32 [100000, 512]
//   d_in[1] = edge_index (unused)
//   d_in[2] = edge_attr  (unused)
//   d_in[3] = batch      int64-or-int32 [100000] (probed)
//   d_in[4] = W          float32 [7, 512]
//   d_in[5] = b          float32 [7]
// Output: float32 [1024, 7]
// ---------------------------------------------------------------------------
extern "C" void kernel_launch(void* const* d_in, const int* in_sizes, int n_in,
                              void* d_out, int out_size)
{
    const float4* x4  = (const float4*)d_in[0];
    const int*    bw  = (const int*)d_in[3];
    const float4* W4g = (const float4*)d_in[4];
    const float*  b   = (const float*)d_in[5];
    float*        out = (float*)d_out;

    const int N = in_sizes[3];

    // 1) zero tiny scratch + dtype probe
    {
        int total = NGROUPS * OUTK;   // 7168 covers g_cnt too
        zero_probe_kernel<<<(total + 255) / 256, 256>>>(bw, N);
    }

    // 2) fused segment-sum + projection
    fused_kernel<<<(N + NPB - 1) / NPB, 128>>>(x4, bw, W4g, N);

    // 3) divide by count + bias
    finalize_kernel<<<OUTK, NGROUPS>>>(b, out);
}

// round 4
// speedup vs baseline: 1.0899x; 1.0899x over previous
#include <cuda_runtime.h>
#include <cuda_bf16.h>
#include <cstdint>

#define F_DIM   512
#define F4      (F_DIM / 4)     // 128 float4 per row
#define NGROUPS 1024
#define OUTK    7
#define TPB     256             // two 128-thread row-teams

// ---------------------------------------------------------------------------
// Single fused kernel. Block b owns group b exclusively (batch is sorted):
//   range = [lower_bound(batch, b), lower_bound(batch, b+1))
// Sums x rows in that range (thread t%128 owns float4 column, two row-teams
// split the range), dots against W, writes out[b][:] = sum·Wᵀ/cnt + b.
// No scratch, no atomics, no zero pass.
// ---------------------------------------------------------------------------
__global__ __launch_bounds__(TPB)
void mognn_kernel(const float4* __restrict__ x4,
                  const int*    __restrict__ bw,   // batch as 32-bit words
                  const float4* __restrict__ W4g,
                  const float*  __restrict__ bias,
                  float*        __restrict__ out,
                  int N)
{
    const int g = blockIdx.x;
    const int t = threadIdx.x;

    // --- dtype probe (batch sorted 0..1023, last element nonzero):
    // int64 storage => odd 32-bit words (high words) are zero.
    const bool is64 = (bw[N - 1] == 0) && (bw[N - 3] == 0) && (bw[N - 5] == 0);

    // --- binary search: lo = first i with batch[i] >= g,
    //                    hi = first i with batch[i] >= g+1
    auto bval = [&](int i) -> int { return is64 ? bw[2 * i] : bw[i]; };
    int lo;
    {
        int a = 0, c = N;
        while (a < c) { int m = (a + c) >> 1; if (bval(m) < g) a = m + 1; else c = m; }
        lo = a;
    }
    int hi;
    {
        int a = lo, c = N;
        while (a < c) { int m = (a + c) >> 1; if (bval(m) < g + 1) a = m + 1; else c = m; }
        hi = a;
    }
    const int cnt = hi - lo;

    // --- split range between two row-teams (contiguous halves)
    const int team = t >> 7;           // 0 or 1
    const int col  = t & 127;          // float4 column this thread owns
    const int mid  = lo + (cnt >> 1);
    int r0 = team ? mid : lo;
    int r1 = team ? hi  : mid;

    // --- stream rows, 2 independent accumulators (MLP ~4 with float4 pairs)
    float4 a0 = make_float4(0.f, 0.f, 0.f, 0.f);
    float4 a1 = make_float4(0.f, 0.f, 0.f, 0.f);
    int r = r0;
    for (; r + 2 <= r1; r += 2) {
        float4 v0 = x4[(size_t)r       * F4 + col];
        float4 v1 = x4[(size_t)(r + 1) * F4 + col];
        a0.x += v0.x; a0.y += v0.y; a0.z += v0.z; a0.w += v0.w;
        a1.x += v1.x; a1.y += v1.y; a1.z += v1.z; a1.w += v1.w;
    }
    if (r < r1) {
        float4 v = x4[(size_t)r * F4 + col];
        a0.x += v.x; a0.y += v.y; a0.z += v.z; a0.w += v.w;
    }
    a0.x += a1.x; a0.y += a1.y; a0.z += a1.z; a0.w += a1.w;

    // --- 7 partial dots against W (read straight from global; W is tiny and
    // L2-resident across all 1024 blocks)
    float p[OUTK];
    #pragma unroll
    for (int k = 0; k < OUTK; k++) {
        float4 w = __ldg(&W4g[k * F4 + col]);
        p[k] = a0.x * w.x + a0.y * w.y + a0.z * w.z + a0.w * w.w;
    }

    // --- reduce across 8 warps
    #pragma unroll
    for (int off = 16; off > 0; off >>= 1) {
        #pragma unroll
        for (int k = 0; k < OUTK; k++)
            p[k] += __shfl_xor_sync(0xffffffff, p[k], off);
    }

    __shared__ float red[8][OUTK];
    const int warp = t >> 5, lane = t & 31;
    if (lane == 0) {
        #pragma unroll
        for (int k = 0; k < OUTK; k++) red[warp][k] = p[k];
    }
    __syncthreads();

    if (t < OUTK) {
        float v = 0.f;
        #pragma unroll
        for (int w = 0; w < 8; w++) v += red[w][t];
        out[g * OUTK + t] = v / fmaxf((float)cnt, 1.0f) + bias[t];
    }
}

// ---------------------------------------------------------------------------
// Inputs (metadata order):
//   d_in[0] = x          float32 [100000, 512]
//   d_in[1] = edge_index (unused)
//   d_in[2] = edge_attr  (unused)
//   d_in[3] = batch      int64-or-int32 [100000] (probed in-kernel)
//   d_in[4] = W          float32 [7, 512]
//   d_in[5] = b          float32 [7]
// Output: float32 [1024, 7]
// ---------------------------------------------------------------------------
extern "C" void kernel_launch(void* const* d_in, const int* in_sizes, int n_in,
                              void* d_out, int out_size)
{
    const float4* x4  = (const float4*)d_in[0];
    const int*    bw  = (const int*)d_in[3];
    const float4* W4g = (const float4*)d_in[4];
    const float*  b   = (const float*)d_in[5];
    float*        out = (float*)d_out;

    const int N = in_sizes[3];

    mognn_kernel<<<NGROUPS, TPB>>>(x4, bw, W4g, b, out, N);
}

// round 5
// speedup vs baseline: 1.1591x; 1.0635x over previous
#include <cuda_runtime.h>
#include <cuda_bf16.h>
#include <cstdint>

#define F_DIM   512
#define F4      (F_DIM / 4)     // 128 float4 per row
#define NGROUPS 1024
#define OUTK    7
#define TPB     256             // two 128-thread row-teams

// ---------------------------------------------------------------------------
// Single fused kernel. Block g owns group g exclusively (batch is sorted):
//   range = [lower_bound(batch, g), lower_bound(batch, g+1))
// Bounds found with a block-cooperative 2-round probe (parallel loads, not a
// serial binary search). Then sum x rows (thread t%128 owns one float4
// column, two row-teams split the range, 4-deep load pipelining), dot with W,
// write out[g][:] = sum·Wᵀ/cnt + bias. No scratch, no atomics.
// ---------------------------------------------------------------------------
__global__ __launch_bounds__(TPB)
void mognn_kernel(const float4* __restrict__ x4,
                  const int*    __restrict__ bw,   // batch as 32-bit words
                  const float4* __restrict__ W4g,
                  const float*  __restrict__ bias,
                  float*        __restrict__ out,
                  int N)
{
    const int g = blockIdx.x;
    const int t = threadIdx.x;
    const int warp = t >> 5, lane = t & 31;

    // --- dtype probe (batch sorted 0..1023, last element nonzero):
    // int64 storage => odd 32-bit words (high words) are zero. L2-hot.
    const bool is64 = (bw[N - 1] == 0) && (bw[N - 3] == 0) && (bw[N - 5] == 0);
    auto bval = [&](int i) -> int { return is64 ? bw[2 * i] : bw[i]; };

    // --- cooperative bounds: lo = first i with batch[i] >= g,
    //                          hi = first i with batch[i] >= g+1.
    // Round 1: 256 probes at stride ~N/256. Round 2: 256 probes inside the
    // bracket. Max-reduce "last index with val < g" via smem.
    __shared__ int sred_lo[8], sred_hi[8];
    __shared__ float redw[8][OUTK];

    int lo = 0, hi = 0;
    {
        const int stride1 = (N + TPB - 1) / TPB;        // ~391
        int idx = min(t * stride1, N - 1);
        int v = bval(idx);
        // candidate: largest probed idx with v < g  (plus stride reach)
        int c_lo = (v < g)     ? idx : -1;
        int c_hi = (v < g + 1) ? idx : -1;
        #pragma unroll
        for (int off = 16; off > 0; off >>= 1) {
            c_lo = max(c_lo, __shfl_xor_sync(0xffffffff, c_lo, off));
            c_hi = max(c_hi, __shfl_xor_sync(0xffffffff, c_hi, off));
        }
        if (lane == 0) { sred_lo[warp] = c_lo; sred_hi[warp] = c_hi; }
        __syncthreads();
        int a_lo = -1, a_hi = -1;
        #pragma unroll
        for (int w = 0; w < 8; w++) {
            a_lo = max(a_lo, sred_lo[w]);
            a_hi = max(a_hi, sred_hi[w]);
        }
        // bracket for lo: (a_lo, a_lo + stride1]; value at a_lo is < g (or a_lo=-1)
        // Round 2: probe every position in the bracket (stride1 <= 391 > 256,
        // so use stride 2 then fix up with one extra check).
        const int stride2 = (stride1 + TPB - 1) / TPB;  // ~2
        // ---- refine lo
        {
            int base = a_lo + 1;                         // first candidate
            int idx2 = min(base + t * stride2, N - 1);
            int v2 = (base + t * stride2 < N) ? bval(idx2) : (NGROUPS + 1);
            int cl = (v2 < g) ? idx2 : -1;
            #pragma unroll
            for (int off = 16; off > 0; off >>= 1)
                cl = max(cl, __shfl_xor_sync(0xffffffff, cl, off));
            if (lane == 0) sred_lo[warp] = cl;
            __syncthreads();
            int best = a_lo;
            #pragma unroll
            for (int w = 0; w < 8; w++) best = max(best, sred_lo[w]);
            // best = largest probed idx with val < g; true boundary within stride2
            int p = best + 1;
            while (p < N && bval(p) < g) p++;            // <= stride2 steps
            lo = p;
        }
        __syncthreads();
        // ---- refine hi
        {
            int base = a_hi + 1;
            int idx2 = min(base + t * stride2, N - 1);
            int v2 = (base + t * stride2 < N) ? bval(idx2) : (NGROUPS + 1);
            int ch = (v2 < g + 1) ? idx2 : -1;
            #pragma unroll
            for (int off = 16; off > 0; off >>= 1)
                ch = max(ch, __shfl_xor_sync(0xffffffff, ch, off));
            if (lane == 0) sred_hi[warp] = ch;
            __syncthreads();
            int best = a_hi;
            #pragma unroll
            for (int w = 0; w < 8; w++) best = max(best, sred_hi[w]);
            int p = best + 1;
            while (p < N && bval(p) < g + 1) p++;
            hi = p;
        }
    }
    const int cnt = hi - lo;

    // --- split rows between two row-teams (contiguous halves)
    const int team = t >> 7;
    const int col  = t & 127;
    const int mid  = lo + (cnt >> 1);
    const int r0 = team ? mid : lo;
    const int r1 = team ? hi  : mid;

    // --- stream rows: 4 independent accumulators, 4 loads in flight
    float4 a0 = make_float4(0.f, 0.f, 0.f, 0.f);
    float4 a1 = make_float4(0.f, 0.f, 0.f, 0.f);
    float4 a2 = make_float4(0.f, 0.f, 0.f, 0.f);
    float4 a3 = make_float4(0.f, 0.f, 0.f, 0.f);
    int r = r0;
    for (; r + 4 <= r1; r += 4) {
        float4 v0 = x4[(size_t)(r + 0) * F4 + col];
        float4 v1 = x4[(size_t)(r + 1) * F4 + col];
        float4 v2 = x4[(size_t)(r + 2) * F4 + col];
        float4 v3 = x4[(size_t)(r + 3) * F4 + col];
        a0.x += v0.x; a0.y += v0.y; a0.z += v0.z; a0.w += v0.w;
        a1.x += v1.x; a1.y += v1.y; a1.z += v1.z; a1.w += v1.w;
        a2.x += v2.x; a2.y += v2.y; a2.z += v2.z; a2.w += v2.w;
        a3.x += v3.x; a3.y += v3.y; a3.z += v3.z; a3.w += v3.w;
    }
    for (; r < r1; r++) {
        float4 v = x4[(size_t)r * F4 + col];
        a0.x += v.x; a0.y += v.y; a0.z += v.z; a0.w += v.w;
    }
    a0.x += a1.x; a0.y += a1.y; a0.z += a1.z; a0.w += a1.w;
    a2.x += a3.x; a2.y += a3.y; a2.z += a3.z; a2.w += a3.w;
    a0.x += a2.x; a0.y += a2.y; a0.z += a2.z; a0.w += a2.w;

    // --- 7 partial dots against W (tiny, L2-resident)
    float p[OUTK];
    #pragma unroll
    for (int k = 0; k < OUTK; k++) {
        float4 w = __ldg(&W4g[k * F4 + col]);
        p[k] = a0.x * w.x + a0.y * w.y + a0.z * w.z + a0.w * w.w;
    }

    // --- reduce across 8 warps
    #pragma unroll
    for (int off = 16; off > 0; off >>= 1) {
        #pragma unroll
        for (int k = 0; k < OUTK; k++)
            p[k] += __shfl_xor_sync(0xffffffff, p[k], off);
    }
    __syncthreads();   // protect sred_* reuse ordering w.r.t. redw
    if (lane == 0) {
        #pragma unroll
        for (int k = 0; k < OUTK; k++) redw[warp][k] = p[k];
    }
    __syncthreads();

    if (t < OUTK) {
        float v = 0.f;
        #pragma unroll
        for (int w = 0; w < 8; w++) v += redw[w][t];
        out[g * OUTK + t] = v / fmaxf((float)cnt, 1.0f) + bias[t];
    }
}

// ---------------------------------------------------------------------------
// Inputs (metadata order):
//   d_in[0] = x          float32 [100000, 512]
//   d_in[1] = edge_index (unused)
//   d_in[2] = edge_attr  (unused)
//   d_in[3] = batch      int64-or-int32 [100000] (probed in-kernel)
//   d_in[4] = W          float32 [7, 512]
//   d_in[5] = b          float32 [7]
// Output: float32 [1024, 7]
// ---------------------------------------------------------------------------
extern "C" void kernel_launch(void* const* d_in, const int* in_sizes, int n_in,
                              void* d_out, int out_size)
{
    const float4* x4  = (const float4*)d_in[0];
    const int*    bw  = (const int*)d_in[3];
    const float4* W4g = (const float4*)d_in[4];
    const float*  b   = (const float*)d_in[5];
    float*        out = (float*)d_out;

    const int N = in_sizes[3];

    mognn_kernel<<<NGROUPS, TPB>>>(x4, bw, W4g, b, out, N);
}

// round 6
// speedup vs baseline: 1.2753x; 1.1002x over previous
#include <cuda_runtime.h>
#include <cuda_bf16.h>
#include <cstdint>

#define F_DIM   512
#define F4      (F_DIM / 4)     // 128 float4 per row
#define NGROUPS 1024
#define OUTK    7
#define TPB     128             // one float4 column per thread, 4 warps

// ---------------------------------------------------------------------------
// Single fused kernel, single-wave geometry: 1024 blocks x 128 threads
// (7 blocks/SM -> all CTAs resident in one wave).
// Block g owns group g exclusively (batch is sorted):
//   range = [lower_bound(batch, g), lower_bound(batch, g+1))
// found by a block-cooperative multi-round probe. Then stream the rows with
// an 8-deep load pipeline, dot with W, write out[g][:] = sum·Wᵀ/cnt + bias.
// No scratch, no atomics, no extra launches.
// ---------------------------------------------------------------------------
__global__ __launch_bounds__(TPB, 7)
void mognn_kernel(const float4* __restrict__ x4,
                  const int*    __restrict__ bw,   // batch as 32-bit words
                  const float4* __restrict__ W4g,
                  const float*  __restrict__ bias,
                  float*        __restrict__ out,
                  int N)
{
    const int g = blockIdx.x;
    const int t = threadIdx.x;          // 0..127 == float4 column
    const int warp = t >> 5, lane = t & 31;

    // --- dtype probe (batch sorted 0..1023, last element nonzero):
    // int64 storage => odd 32-bit words (high words) are zero. L2-hot.
    const bool is64 = (bw[N - 1] == 0) && (bw[N - 3] == 0) && (bw[N - 5] == 0);
    auto bval = [&](int i) -> int { return is64 ? bw[2 * i] : bw[i]; };

    // --- cooperative bounds: lo = first i with batch[i] >= g,
    //                          hi = first i with batch[i] >= g+1.
    __shared__ int sred_lo[4], sred_hi[4];
    __shared__ float redw[4][OUTK];

    int lo, hi;
    {
        const int stride1 = (N + TPB - 1) / TPB;         // ~782
        int idx = min(t * stride1, N - 1);
        int v = bval(idx);
        int c_lo = (v < g)     ? idx : -1;
        int c_hi = (v < g + 1) ? idx : -1;
        #pragma unroll
        for (int off = 16; off > 0; off >>= 1) {
            c_lo = max(c_lo, __shfl_xor_sync(0xffffffff, c_lo, off));
            c_hi = max(c_hi, __shfl_xor_sync(0xffffffff, c_hi, off));
        }
        if (lane == 0) { sred_lo[warp] = c_lo; sred_hi[warp] = c_hi; }
        __syncthreads();
        int a_lo = max(max(sred_lo[0], sred_lo[1]), max(sred_lo[2], sred_lo[3]));
        int a_hi = max(max(sred_hi[0], sred_hi[1]), max(sred_hi[2], sred_hi[3]));
        __syncthreads();

        const int stride2 = (stride1 + TPB - 1) / TPB;   // ~7
        // ---- refine lo (bracket (a_lo, a_lo+stride1])
        {
            int base = a_lo + 1;
            int pos = base + t * stride2;
            int v2 = (pos < N) ? bval(min(pos, N - 1)) : (NGROUPS + 1);
            int cl = (v2 < g) ? pos : -1;
            #pragma unroll
            for (int off = 16; off > 0; off >>= 1)
                cl = max(cl, __shfl_xor_sync(0xffffffff, cl, off));
            if (lane == 0) sred_lo[warp] = cl;
            __syncthreads();
            int best = max(max(sred_lo[0], sred_lo[1]), max(sred_lo[2], sred_lo[3]));
            best = max(best, a_lo);
            int p = best + 1;
            while (p < N && bval(p) < g) p++;            // <= stride2 steps
            lo = p;
            __syncthreads();
        }
        // ---- refine hi
        {
            int base = a_hi + 1;
            int pos = base + t * stride2;
            int v2 = (pos < N) ? bval(min(pos, N - 1)) : (NGROUPS + 1);
            int ch = (v2 < g + 1) ? pos : -1;
            #pragma unroll
            for (int off = 16; off > 0; off >>= 1)
                ch = max(ch, __shfl_xor_sync(0xffffffff, ch, off));
            if (lane == 0) sred_hi[warp] = ch;
            __syncthreads();
            int best = max(max(sred_hi[0], sred_hi[1]), max(sred_hi[2], sred_hi[3]));
            best = max(best, a_hi);
            int p = best + 1;
            while (p < N && bval(p) < g + 1) p++;
            hi = p;
        }
    }
    const int cnt = hi - lo;

    // --- stream rows: 8 independent loads in flight, 4 accumulators
    float4 a0 = make_float4(0.f, 0.f, 0.f, 0.f);
    float4 a1 = make_float4(0.f, 0.f, 0.f, 0.f);
    float4 a2 = make_float4(0.f, 0.f, 0.f, 0.f);
    float4 a3 = make_float4(0.f, 0.f, 0.f, 0.f);
    int r = lo;
    for (; r + 8 <= hi; r += 8) {
        float4 v0 = x4[(size_t)(r + 0) * F4 + t];
        float4 v1 = x4[(size_t)(r + 1) * F4 + t];
        float4 v2 = x4[(size_t)(r + 2) * F4 + t];
        float4 v3 = x4[(size_t)(r + 3) * F4 + t];
        float4 v4 = x4[(size_t)(r + 4) * F4 + t];
        float4 v5 = x4[(size_t)(r + 5) * F4 + t];
        float4 v6 = x4[(size_t)(r + 6) * F4 + t];
        float4 v7 = x4[(size_t)(r + 7) * F4 + t];
        a0.x += v0.x; a0.y += v0.y; a0.z += v0.z; a0.w += v0.w;
        a1.x += v1.x; a1.y += v1.y; a1.z += v1.z; a1.w += v1.w;
        a2.x += v2.x; a2.y += v2.y; a2.z += v2.z; a2.w += v2.w;
        a3.x += v3.x; a3.y += v3.y; a3.z += v3.z; a3.w += v3.w;
        a0.x += v4.x; a0.y += v4.y; a0.z += v4.z; a0.w += v4.w;
        a1.x += v5.x; a1.y += v5.y; a1.z += v5.z; a1.w += v5.w;
        a2.x += v6.x; a2.y += v6.y; a2.z += v6.z; a2.w += v6.w;
        a3.x += v7.x; a3.y += v7.y; a3.z += v7.z; a3.w += v7.w;
    }
    for (; r < hi; r++) {
        float4 v = x4[(size_t)r * F4 + t];
        a0.x += v.x; a0.y += v.y; a0.z += v.z; a0.w += v.w;
    }
    a0.x += a1.x; a0.y += a1.y; a0.z += a1.z; a0.w += a1.w;
    a2.x += a3.x; a2.y += a3.y; a2.z += a3.z; a2.w += a3.w;
    a0.x += a2.x; a0.y += a2.y; a0.z += a2.z; a0.w += a2.w;

    // --- 7 partial dots against W (tiny, L2-resident)
    float p[OUTK];
    #pragma unroll
    for (int k = 0; k < OUTK; k++) {
        float4 w = __ldg(&W4g[k * F4 + t]);
        p[k] = a0.x * w.x + a0.y * w.y + a0.z * w.z + a0.w * w.w;
    }

    // --- reduce across 4 warps
    #pragma unroll
    for (int off = 16; off > 0; off >>= 1) {
        #pragma unroll
        for (int k = 0; k < OUTK; k++)
            p[k] += __shfl_xor_sync(0xffffffff, p[k], off);
    }
    __syncthreads();
    if (lane == 0) {
        #pragma unroll
        for (int k = 0; k < OUTK; k++) redw[warp][k] = p[k];
    }
    __syncthreads();

    if (t < OUTK) {
        float v = redw[0][t] + redw[1][t] + redw[2][t] + redw[3][t];
        out[g * OUTK + t] = v / fmaxf((float)cnt, 1.0f) + bias[t];
    }
}

// ---------------------------------------------------------------------------
// Inputs (metadata order):
//   d_in[0] = x          float32 [100000, 512]
//   d_in[1] = edge_index (unused)
//   d_in[2] = edge_attr  (unused)
//   d_in[3] = batch      int64-or-int32 [100000] (probed in-kernel)
//   d_in[4] = W          float32 [7, 512]
//   d_in[5] = b          float32 [7]
// Output: float32 [1024, 7]
// ---------------------------------------------------------------------------
extern "C" void kernel_launch(void* const* d_in, const int* in_sizes, int n_in,
                              void* d_out, int out_size)
{
    const float4* x4  = (const float4*)d_in[0];
    const int*    bw  = (const int*)d_in[3];
    const float4* W4g = (const float4*)d_in[4];
    const float*  b   = (const float*)d_in[5];
    float*        out = (float*)d_out;

    const int N = in_sizes[3];

    mognn_kernel<<<NGROUPS, TPB>>>(x4, bw, W4g, b, out, N);
}

// round 7
// speedup vs baseline: 1.3288x; 1.0420x over previous
#include <cuda_runtime.h>
#include <cuda_bf16.h>
#include <cstdint>

#define F_DIM   512
#define F4      (F_DIM / 4)     // 128 float4 per row
#define NGROUPS 1024
#define OUTK    7
#define TPB     128             // one float4 column per thread, 4 warps

// ---------------------------------------------------------------------------
// Single fused kernel. Block g owns group g exclusively (batch is sorted):
//   [lo, hi) = [lower_bound(batch, g), lower_bound(batch, g+1))
// found by a fully parallel 3-round probe (no serial pointer chase):
//   round 1: 128 probes @ stride ~782 (one load serves both bounds)
//   round 2: warps {0,1} refine lo, warps {2,3} refine hi @ stride 13
//   round 3: same teams probe the final <=13 slots in one parallel load
// Then stream rows with an 8-deep load pipeline and pointer increments,
// dot with W, write out[g][:] = sum·Wᵀ/cnt + bias.
// ---------------------------------------------------------------------------
__global__ __launch_bounds__(TPB, 8)
void mognn_kernel(const float4* __restrict__ x4,
                  const int*    __restrict__ bw,   // batch as 32-bit words
                  const float4* __restrict__ W4g,
                  const float*  __restrict__ bias,
                  float*        __restrict__ out,
                  int N)
{
    const int g = blockIdx.x;
    const int t = threadIdx.x;          // 0..127 == float4 column
    const int warp = t >> 5, lane = t & 31;

    // --- dtype probe (batch sorted 0..1023, last element nonzero):
    // int64 storage => odd 32-bit words (high words) are zero. L2-hot.
    const bool is64 = (bw[N - 1] == 0) && (bw[N - 3] == 0) && (bw[N - 5] == 0);
    auto bval = [&](int i) -> int { return is64 ? bw[2 * i] : bw[i]; };

    __shared__ int  sm[4];
    __shared__ float redw[4][OUTK];

    const int BIG = NGROUPS + 1;
    // team: warps 0,1 -> lo (target g); warps 2,3 -> hi (target g+1)
    const int team   = (t >= 64);
    const int tt     = t & 63;
    const int target = team ? (g + 1) : g;

    int lo, hi;
    {
        // ---- round 1: shared probes @ stride1
        const int stride1 = (N + TPB - 1) / TPB;          // 782 for N=100000
        int idx = min(t * stride1, N - 1);
        int v = bval(idx);
        int c_lo = (v < g)     ? idx : -1;
        int c_hi = (v < g + 1) ? idx : -1;
        #pragma unroll
        for (int off = 16; off > 0; off >>= 1) {
            c_lo = max(c_lo, __shfl_xor_sync(0xffffffff, c_lo, off));
            c_hi = max(c_hi, __shfl_xor_sync(0xffffffff, c_hi, off));
        }
        if (lane == 0) { sm[warp] = c_lo; }
        __syncthreads();
        int a_lo = max(max(sm[0], sm[1]), max(sm[2], sm[3]));
        __syncthreads();
        if (lane == 0) { sm[warp] = c_hi; }
        __syncthreads();
        int a_hi = max(max(sm[0], sm[1]), max(sm[2], sm[3]));
        __syncthreads();
        // boundary_lo in (a_lo, a_lo+stride1], same for hi.

        // ---- round 2: two teams, stride2 probes
        const int stride2 = (stride1 + 63) / 64;          // 13
        int abase = team ? a_hi : a_lo;
        int pos = abase + 1 + tt * stride2;
        int v2 = (pos < N) ? bval(pos) : BIG;
        int c = (v2 < target) ? pos : -1;
        #pragma unroll
        for (int off = 16; off > 0; off >>= 1)
            c = max(c, __shfl_xor_sync(0xffffffff, c, off));
        if (lane == 0) sm[warp] = c;
        __syncthreads();
        int best_lo = max(a_lo, max(sm[0], sm[1]));
        int best_hi = max(a_hi, max(sm[2], sm[3]));
        __syncthreads();
        // boundary in (best, best+stride2]

        // ---- round 3: final <=stride2 positions, one parallel load
        abase = team ? best_hi : best_lo;
        pos = abase + 1 + tt;
        int v3 = (tt < stride2 && pos < N) ? bval(pos) : BIG;
        c = (v3 < target) ? pos : -1;
        #pragma unroll
        for (int off = 16; off > 0; off >>= 1)
            c = max(c, __shfl_xor_sync(0xffffffff, c, off));
        if (lane == 0) sm[warp] = c;
        __syncthreads();
        lo = max(best_lo, max(sm[0], sm[1])) + 1;
        hi = max(best_hi, max(sm[2], sm[3])) + 1;
    }
    const int cnt = hi - lo;

    // --- stream rows: 8 independent loads in flight, 4 accumulators,
    //     pointer-increment addressing
    float4 a0 = make_float4(0.f, 0.f, 0.f, 0.f);
    float4 a1 = make_float4(0.f, 0.f, 0.f, 0.f);
    float4 a2 = make_float4(0.f, 0.f, 0.f, 0.f);
    float4 a3 = make_float4(0.f, 0.f, 0.f, 0.f);
    const float4* p = x4 + (size_t)lo * F4 + t;
    int n = cnt;
    for (; n >= 8; n -= 8, p += 8 * F4) {
        float4 v0 = p[0 * F4];
        float4 v1 = p[1 * F4];
        float4 v2 = p[2 * F4];
        float4 v3 = p[3 * F4];
        float4 v4 = p[4 * F4];
        float4 v5 = p[5 * F4];
        float4 v6 = p[6 * F4];
        float4 v7 = p[7 * F4];
        a0.x += v0.x; a0.y += v0.y; a0.z += v0.z; a0.w += v0.w;
        a1.x += v1.x; a1.y += v1.y; a1.z += v1.z; a1.w += v1.w;
        a2.x += v2.x; a2.y += v2.y; a2.z += v2.z; a2.w += v2.w;
        a3.x += v3.x; a3.y += v3.y; a3.z += v3.z; a3.w += v3.w;
        a0.x += v4.x; a0.y += v4.y; a0.z += v4.z; a0.w += v4.w;
        a1.x += v5.x; a1.y += v5.y; a1.z += v5.z; a1.w += v5.w;
        a2.x += v6.x; a2.y += v6.y; a2.z += v6.z; a2.w += v6.w;
        a3.x += v7.x; a3.y += v7.y; a3.z += v7.z; a3.w += v7.w;
    }
    for (; n > 0; n--, p += F4) {
        float4 v = p[0];
        a0.x += v.x; a0.y += v.y; a0.z += v.z; a0.w += v.w;
    }
    a0.x += a1.x; a0.y += a1.y; a0.z += a1.z; a0.w += a1.w;
    a2.x += a3.x; a2.y += a3.y; a2.z += a3.z; a2.w += a3.w;
    a0.x += a2.x; a0.y += a2.y; a0.z += a2.z; a0.w += a2.w;

    // --- 7 partial dots against W (tiny, L2-resident)
    float pr[OUTK];
    #pragma unroll
    for (int k = 0; k < OUTK; k++) {
        float4 w = __ldg(&W4g[k * F4 + t]);
        pr[k] = a0.x * w.x + a0.y * w.y + a0.z * w.z + a0.w * w.w;
    }

    // --- reduce across 4 warps
    #pragma unroll
    for (int off = 16; off > 0; off >>= 1) {
        #pragma unroll
        for (int k = 0; k < OUTK; k++)
            pr[k] += __shfl_xor_sync(0xffffffff, pr[k], off);
    }
    if (lane == 0) {
        #pragma unroll
        for (int k = 0; k < OUTK; k++) redw[warp][k] = pr[k];
    }
    __syncthreads();

    if (t < OUTK) {
        float v = redw[0][t] + redw[1][t] + redw[2][t] + redw[3][t];
        out[g * OUTK + t] = v / fmaxf((float)cnt, 1.0f) + bias[t];
    }
}

// ---------------------------------------------------------------------------
// Inputs (metadata order):
//   d_in[0] = x          float32 [100000, 512]
//   d_in[1] = edge_index (unused)
//   d_in[2] = edge_attr  (unused)
//   d_in[3] = batch      int64-or-int32 [100000] (probed in-kernel)
//   d_in[4] = W          float32 [7, 512]
//   d_in[5] = b          float32 [7]
// Output: float32 [1024, 7]
// ---------------------------------------------------------------------------
extern "C" void kernel_launch(void* const* d_in, const int* in_sizes, int n_in,
                              void* d_out, int out_size)
{
    const float4* x4  = (const float4*)d_in[0];
    const int*    bw  = (const int*)d_in[3];
    const float4* W4g = (const float4*)d_in[4];
    const float*  b   = (const float*)d_in[5];
    float*        out = (float*)d_out;

    const int N = in_sizes[3];

    mognn_kernel<<<NGROUPS, TPB>>>(x4, bw, W4g, b, out, N);
}

// round 8
// speedup vs baseline: 1.3299x; 1.0009x over previous
#include <cuda_runtime.h>
#include <cuda_bf16.h>
#include <cstdint>

#define F_DIM   512
#define F4      (F_DIM / 4)     // 128 float4 per row
#define NGROUPS 1024
#define OUTK    7
#define TPB     128             // one float4 column per thread, 4 warps

// ---------------------------------------------------------------------------
// Single fused kernel. Block g owns group g exclusively (batch is sorted):
//   [lo, hi) = [lower_bound(batch, g), lower_bound(batch, g+1))
// found by a fully parallel 3-round probe. Then stream rows with an 8-deep
// load pipeline using evict-first (streaming) loads — x is read exactly once
// and must not pollute L2 — dot with W, write out[g][:] = sum·Wᵀ/cnt + bias.
// ---------------------------------------------------------------------------
__global__ __launch_bounds__(TPB, 8)
void mognn_kernel(const float4* __restrict__ x4,
                  const int*    __restrict__ bw,   // batch as 32-bit words
                  const float4* __restrict__ W4g,
                  const float*  __restrict__ bias,
                  float*        __restrict__ out,
                  int N)
{
    const int g = blockIdx.x;
    const int t = threadIdx.x;          // 0..127 == float4 column
    const int warp = t >> 5, lane = t & 31;

    // --- dtype probe (batch sorted 0..1023, last element nonzero):
    // int64 storage => odd 32-bit words (high words) are zero. L2-hot.
    const bool is64 = (bw[N - 1] == 0) && (bw[N - 3] == 0) && (bw[N - 5] == 0);
    auto bval = [&](int i) -> int { return is64 ? bw[2 * i] : bw[i]; };

    __shared__ int  sm[4];
    __shared__ float redw[4][OUTK];

    const int BIG = NGROUPS + 1;
    // team: warps 0,1 -> lo (target g); warps 2,3 -> hi (target g+1)
    const int team   = (t >= 64);
    const int tt     = t & 63;
    const int target = team ? (g + 1) : g;

    int lo, hi;
    {
        // ---- round 1: shared probes @ stride1
        const int stride1 = (N + TPB - 1) / TPB;          // 782 for N=100000
        int idx = min(t * stride1, N - 1);
        int v = bval(idx);
        int c_lo = (v < g)     ? idx : -1;
        int c_hi = (v < g + 1) ? idx : -1;
        #pragma unroll
        for (int off = 16; off > 0; off >>= 1) {
            c_lo = max(c_lo, __shfl_xor_sync(0xffffffff, c_lo, off));
            c_hi = max(c_hi, __shfl_xor_sync(0xffffffff, c_hi, off));
        }
        if (lane == 0) { sm[warp] = c_lo; }
        __syncthreads();
        int a_lo = max(max(sm[0], sm[1]), max(sm[2], sm[3]));
        __syncthreads();
        if (lane == 0) { sm[warp] = c_hi; }
        __syncthreads();
        int a_hi = max(max(sm[0], sm[1]), max(sm[2], sm[3]));
        __syncthreads();
        // boundary_lo in (a_lo, a_lo+stride1], same for hi.

        // ---- round 2: two teams, stride2 probes
        const int stride2 = (stride1 + 63) / 64;          // 13
        int abase = team ? a_hi : a_lo;
        int pos = abase + 1 + tt * stride2;
        int v2 = (pos < N) ? bval(pos) : BIG;
        int c = (v2 < target) ? pos : -1;
        #pragma unroll
        for (int off = 16; off > 0; off >>= 1)
            c = max(c, __shfl_xor_sync(0xffffffff, c, off));
        if (lane == 0) sm[warp] = c;
        __syncthreads();
        int best_lo = max(a_lo, max(sm[0], sm[1]));
        int best_hi = max(a_hi, max(sm[2], sm[3]));
        __syncthreads();
        // boundary in (best, best+stride2]

        // ---- round 3: final <=stride2 positions, one parallel load
        abase = team ? best_hi : best_lo;
        pos = abase + 1 + tt;
        int v3 = (tt < stride2 && pos < N) ? bval(pos) : BIG;
        c = (v3 < target) ? pos : -1;
        #pragma unroll
        for (int off = 16; off > 0; off >>= 1)
            c = max(c, __shfl_xor_sync(0xffffffff, c, off));
        if (lane == 0) sm[warp] = c;
        __syncthreads();
        lo = max(best_lo, max(sm[0], sm[1])) + 1;
        hi = max(best_hi, max(sm[2], sm[3])) + 1;
    }
    const int cnt = hi - lo;

    // --- stream rows: 8 streaming (evict-first) loads in flight, 4 accums
    float4 a0 = make_float4(0.f, 0.f, 0.f, 0.f);
    float4 a1 = make_float4(0.f, 0.f, 0.f, 0.f);
    float4 a2 = make_float4(0.f, 0.f, 0.f, 0.f);
    float4 a3 = make_float4(0.f, 0.f, 0.f, 0.f);
    const float4* p = x4 + (size_t)lo * F4 + t;
    int n = cnt;
    for (; n >= 8; n -= 8, p += 8 * F4) {
        float4 v0 = __ldcs(p + 0 * F4);
        float4 v1 = __ldcs(p + 1 * F4);
        float4 v2 = __ldcs(p + 2 * F4);
        float4 v3 = __ldcs(p + 3 * F4);
        float4 v4 = __ldcs(p + 4 * F4);
        float4 v5 = __ldcs(p + 5 * F4);
        float4 v6 = __ldcs(p + 6 * F4);
        float4 v7 = __ldcs(p + 7 * F4);
        a0.x += v0.x; a0.y += v0.y; a0.z += v0.z; a0.w += v0.w;
        a1.x += v1.x; a1.y += v1.y; a1.z += v1.z; a1.w += v1.w;
        a2.x += v2.x; a2.y += v2.y; a2.z += v2.z; a2.w += v2.w;
        a3.x += v3.x; a3.y += v3.y; a3.z += v3.z; a3.w += v3.w;
        a0.x += v4.x; a0.y += v4.y; a0.z += v4.z; a0.w += v4.w;
        a1.x += v5.x; a1.y += v5.y; a1.z += v5.z; a1.w += v5.w;
        a2.x += v6.x; a2.y += v6.y; a2.z += v6.z; a2.w += v6.w;
        a3.x += v7.x; a3.y += v7.y; a3.z += v7.z; a3.w += v7.w;
    }
    for (; n > 0; n--, p += F4) {
        float4 v = __ldcs(p);
        a0.x += v.x; a0.y += v.y; a0.z += v.z; a0.w += v.w;
    }
    a0.x += a1.x; a0.y += a1.y; a0.z += a1.z; a0.w += a1.w;
    a2.x += a3.x; a2.y += a3.y; a2.z += a3.z; a2.w += a3.w;
    a0.x += a2.x; a0.y += a2.y; a0.z += a2.z; a0.w += a2.w;

    // --- 7 partial dots against W (tiny, L2-resident; default caching)
    float pr[OUTK];
    #pragma unroll
    for (int k = 0; k < OUTK; k++) {
        float4 w = __ldg(&W4g[k * F4 + t]);
        pr[k] = a0.x * w.x + a0.y * w.y + a0.z * w.z + a0.w * w.w;
    }

    // --- reduce across 4 warps
    #pragma unroll
    for (int off = 16; off > 0; off >>= 1) {
        #pragma unroll
        for (int k = 0; k < OUTK; k++)
            pr[k] += __shfl_xor_sync(0xffffffff, pr[k], off);
    }
    if (lane == 0) {
        #pragma unroll
        for (int k = 0; k < OUTK; k++) redw[warp][k] = pr[k];
    }
    __syncthreads();

    if (t < OUTK) {
        float v = redw[0][t] + redw[1][t] + redw[2][t] + redw[3][t];
        out[g * OUTK + t] = v / fmaxf((float)cnt, 1.0f) + bias[t];
    }
}

// ---------------------------------------------------------------------------
// Inputs (metadata order):
//   d_in[0] = x          float32 [100000, 512]
//   d_in[1] = edge_index (unused)
//   d_in[2] = edge_attr  (unused)
//   d_in[3] = batch      int64-or-int32 [100000] (probed in-kernel)
//   d_in[4] = W          float32 [7, 512]
//   d_in[5] = b          float32 [7]
// Output: float32 [1024, 7]
// ---------------------------------------------------------------------------
extern "C" void kernel_launch(void* const* d_in, const int* in_sizes, int n_in,
                              void* d_out, int out_size)
{
    const float4* x4  = (const float4*)d_in[0];
    const int*    bw  = (const int*)d_in[3];
    const float4* W4g = (const float4*)d_in[4];
    const float*  b   = (const float*)d_in[5];
    float*        out = (float*)d_out;

    const int N = in_sizes[3];

    mognn_kernel<<<NGROUPS, TPB>>>(x4, bw, W4g, b, out, N);
}